// round 1
// baseline (speedup 1.0000x reference)
#include <cuda_runtime.h>
#include <cstdint>

#define NPIX 4096
#define CB   256
#define BQ   4
#define TM   128
#define SKS  136
#define SPS  132

// Scratch (device globals — no runtime allocation allowed)
__device__ float g_qk[BQ][64][NPIX];   // rows 0..31 = q, 32..63 = k   (4 MB)
__device__ float g_v[BQ][CB][NPIX];    // only used when gamma != 0    (16 MB)

__device__ __forceinline__ float tf32r(float v) {
    uint32_t u;
    asm("cvt.rna.tf32.f32 %0, %1;" : "=r"(u) : "f"(v));
    return __uint_as_float(u);
}

// ---------------------------------------------------------------------------
// Kernel A: q = Wq·sa_D + bq, k = Wk·sa_D + bk  -> g_qk[b][d][n] (tf32-rounded)
// grid (64, 4), block 256. smem: sW[64][258] | sX[64][64] | sB[64]
// ---------------------------------------------------------------------------
__global__ void qk_kernel(const float* __restrict__ saD,
                          const float* __restrict__ Wq, const float* __restrict__ bq,
                          const float* __restrict__ Wk, const float* __restrict__ bk)
{
    extern __shared__ float sm[];
    float* sW = sm;                 // 64*258
    float* sX = sm + 64 * 258;      // 64*64
    float* sB = sX + 64 * 64;       // 64

    int b  = blockIdx.y;
    int n0 = blockIdx.x * 64;
    int t  = threadIdx.x;

    for (int i = t; i < 64 * 256; i += 256) {
        int d = i >> 8, c = i & 255;
        sW[d * 258 + c] = (d < 32) ? Wq[d * 256 + c] : Wk[(d - 32) * 256 + c];
    }
    if (t < 64) sB[t] = (t < 32) ? bq[t] : bk[t - 32];
    __syncthreads();

    int ty = t >> 4, tx = t & 15;
    float acc[4][4];
#pragma unroll
    for (int i = 0; i < 4; i++) {
        float bias = sB[ty + 16 * i];
#pragma unroll
        for (int j = 0; j < 4; j++) acc[i][j] = bias;
    }

    for (int c0 = 0; c0 < 256; c0 += 64) {
        __syncthreads();
        // load sa_D[b, c0:c0+64, n0:n0+64] (float4, coalesced)
#pragma unroll
        for (int r = 0; r < 4; r++) {
            int f  = t + 256 * r;             // float4 index (1024 total)
            int cc = f >> 4, nn = (f & 15) << 2;
            *(float4*)&sX[cc * 64 + nn] =
                *(const float4*)&saD[(size_t)(b * 256 + c0 + cc) * NPIX + n0 + nn];
        }
        __syncthreads();
#pragma unroll 4
        for (int cc = 0; cc < 64; cc++) {
            float w0 = sW[(ty     ) * 258 + c0 + cc];
            float w1 = sW[(ty + 16) * 258 + c0 + cc];
            float w2 = sW[(ty + 32) * 258 + c0 + cc];
            float w3 = sW[(ty + 48) * 258 + c0 + cc];
#pragma unroll
            for (int j = 0; j < 4; j++) {
                float x = sX[cc * 64 + tx + 16 * j];
                acc[0][j] += w0 * x; acc[1][j] += w1 * x;
                acc[2][j] += w2 * x; acc[3][j] += w3 * x;
            }
        }
    }
#pragma unroll
    for (int i = 0; i < 4; i++)
#pragma unroll
        for (int j = 0; j < 4; j++) {
            int d = ty + 16 * i;
            int n = n0 + tx + 16 * j;
            g_qk[b][d][n] = tf32r(acc[i][j]);
        }
}

// ---------------------------------------------------------------------------
// Kernel B: fused energy + softmax + attention write (two-pass, tf32 mma)
// grid (64, 4), block 128 (4 warps, 16 rows each, 64 rows/CTA)
// smem: sQ[64][33] | sK[32][136] | sP[4][16][132]
// ---------------------------------------------------------------------------
__device__ __forceinline__ void mma_tf32(float& c0, float& c1, float& c2, float& c3,
                                         const float a[4], float b0, float b1)
{
    asm volatile(
        "mma.sync.aligned.m16n8k8.row.col.f32.tf32.tf32.f32 "
        "{%0,%1,%2,%3}, {%4,%5,%6,%7}, {%8,%9}, {%0,%1,%2,%3};"
        : "+f"(c0), "+f"(c1), "+f"(c2), "+f"(c3)
        : "r"(__float_as_uint(a[0])), "r"(__float_as_uint(a[1])),
          "r"(__float_as_uint(a[2])), "r"(__float_as_uint(a[3])),
          "r"(__float_as_uint(b0)), "r"(__float_as_uint(b1)));
}

__global__ void attn_kernel(float* __restrict__ att)
{
    extern __shared__ float sm[];
    float* sQ = sm;                  // 64*33
    float* sK = sQ + 64 * 33;        // 32*SKS
    float* sP = sK + 32 * SKS;       // 4*16*SPS

    int b  = blockIdx.y;
    int n0 = blockIdx.x * 64;
    int t  = threadIdx.x, w = t >> 5, l = t & 31;

    const float* qg = &g_qk[b][0][0];
    const float* kg = &g_qk[b][32][0];

    // load Q tile [64 rows n][32 d], transposed from [d][n] layout
    for (int i = t; i < 64 * 32; i += 128) {
        int n = i & 63, d = i >> 6;
        sQ[n * 33 + d] = qg[(size_t)d * NPIX + n0 + n];
    }
    __syncthreads();

    // hoist A fragments (warp owns rows w*16 .. w*16+15)
    float aF[4][4];
    {
        int r = w * 16 + (l >> 2);
#pragma unroll
        for (int kk = 0; kk < 4; kk++) {
            int c = kk * 8 + (l & 3);
            aF[kk][0] = sQ[r * 33 + c];
            aF[kk][1] = sQ[(r + 8) * 33 + c];
            aF[kk][2] = sQ[r * 33 + c + 4];
            aF[kk][3] = sQ[(r + 8) * 33 + c + 4];
        }
    }

    // ---- pass 1: row sums of exp(energy) ----
    float s0 = 0.f, s1 = 0.f;
    for (int m0 = 0; m0 < NPIX; m0 += TM) {
#pragma unroll
        for (int r = 0; r < 8; r++) {
            int f = t + 128 * r;             // float4 index (1024 total)
            int d = f >> 5, mm = (f & 31) << 2;
            *(float4*)&sK[d * SKS + mm] =
                *(const float4*)&kg[(size_t)d * NPIX + m0 + mm];
        }
        __syncthreads();
        for (int j = 0; j < 16; j++) {
            float c0 = 0.f, c1 = 0.f, c2 = 0.f, c3 = 0.f;
#pragma unroll
            for (int kk = 0; kk < 4; kk++) {
                float b0 = sK[(kk * 8 + (l & 3)) * SKS + j * 8 + (l >> 2)];
                float b1 = sK[(kk * 8 + (l & 3) + 4) * SKS + j * 8 + (l >> 2)];
                mma_tf32(c0, c1, c2, c3, aF[kk], b0, b1);
            }
            s0 += __expf(c0) + __expf(c1);
            s1 += __expf(c2) + __expf(c3);
        }
        __syncthreads();
    }
    s0 += __shfl_xor_sync(0xffffffffu, s0, 1);
    s0 += __shfl_xor_sync(0xffffffffu, s0, 2);
    s1 += __shfl_xor_sync(0xffffffffu, s1, 1);
    s1 += __shfl_xor_sync(0xffffffffu, s1, 2);
    float inv0 = 1.f / s0;
    float inv1 = 1.f / s1;

    // ---- pass 2: recompute, normalize, stage, write ----
    float* sPw = sP + w * 16 * SPS;
    for (int m0 = 0; m0 < NPIX; m0 += TM) {
#pragma unroll
        for (int r = 0; r < 8; r++) {
            int f = t + 128 * r;
            int d = f >> 5, mm = (f & 31) << 2;
            *(float4*)&sK[d * SKS + mm] =
                *(const float4*)&kg[(size_t)d * NPIX + m0 + mm];
        }
        __syncthreads();
        for (int j = 0; j < 16; j++) {
            float c0 = 0.f, c1 = 0.f, c2 = 0.f, c3 = 0.f;
#pragma unroll
            for (int kk = 0; kk < 4; kk++) {
                float b0 = sK[(kk * 8 + (l & 3)) * SKS + j * 8 + (l >> 2)];
                float b1 = sK[(kk * 8 + (l & 3) + 4) * SKS + j * 8 + (l >> 2)];
                mma_tf32(c0, c1, c2, c3, aF[kk], b0, b1);
            }
            float p0 = __expf(c0) * inv0, p1 = __expf(c1) * inv0;
            float p2 = __expf(c2) * inv1, p3 = __expf(c3) * inv1;
            int row = l >> 2, col = j * 8 + (l & 3) * 2;
            sPw[row * SPS + col]           = p0;
            sPw[row * SPS + col + 1]       = p1;
            sPw[(row + 8) * SPS + col]     = p2;
            sPw[(row + 8) * SPS + col + 1] = p3;
        }
        __syncwarp();
        // drain warp tile [16][128] -> global, coalesced 512B rows
        for (int r = 0; r < 16; r++) {
            float4 v = *(float4*)&sPw[r * SPS + l * 4];
            *(float4*)&att[(size_t)(b * NPIX + n0 + w * 16 + r) * NPIX + m0 + l * 4] = v;
        }
        __syncthreads();
    }
}

// ---------------------------------------------------------------------------
// Kernel C: v = Wv·sa_E + bv  (only when gamma != 0 — exact skip otherwise)
// ---------------------------------------------------------------------------
__global__ void v_kernel(const float* __restrict__ saE,
                         const float* __restrict__ Wv,
                         const float* __restrict__ bv,
                         const float* __restrict__ gamma)
{
    if (gamma[0] == 0.f) return;
    int total = BQ * CB * NPIX;
    for (int idx = blockIdx.x * blockDim.x + threadIdx.x; idx < total;
         idx += gridDim.x * blockDim.x) {
        int m  = idx & (NPIX - 1);
        int c  = (idx >> 12) & 255;
        int bb = idx >> 20;
        float s = bv[c];
        for (int cc = 0; cc < 256; cc++)
            s += Wv[c * 256 + cc] * saE[(size_t)(bb * 256 + cc) * NPIX + m];
        g_v[bb][c][m] = s;
    }
}

// ---------------------------------------------------------------------------
// Kernel D: out = gamma*(V·A^T) + sa_E.  gamma==0 -> exact copy of sa_E.
// ---------------------------------------------------------------------------
__global__ void out_kernel(const float* __restrict__ saE,
                           const float* __restrict__ gamma,
                           float* __restrict__ out,
                           const float* __restrict__ att)
{
    float g = gamma[0];
    int nvec = (BQ * CB * NPIX) / 4;  // float4 count
    if (g == 0.f) {
        for (int i = blockIdx.x * blockDim.x + threadIdx.x; i < nvec;
             i += gridDim.x * blockDim.x)
            ((float4*)out)[i] = ((const float4*)saE)[i];
    } else {
        for (int i = blockIdx.x * blockDim.x + threadIdx.x; i < nvec;
             i += gridDim.x * blockDim.x) {
            int base = i * 4;
            int n  = base & (NPIX - 1);
            int c  = (base >> 12) & 255;
            int bb = base >> 20;
            float4 e = ((const float4*)saE)[i];
            const float* vrow = &g_v[bb][c][0];
            float rr[4];
#pragma unroll
            for (int jj = 0; jj < 4; jj++) {
                const float* arow = att + (size_t)(bb * NPIX + n + jj) * NPIX;
                float s = 0.f;
                for (int m = 0; m < NPIX; m++) s += vrow[m] * arow[m];
                rr[jj] = g * s + (&e.x)[jj];
            }
            ((float4*)out)[i] = make_float4(rr[0], rr[1], rr[2], rr[3]);
        }
    }
}

// ---------------------------------------------------------------------------
extern "C" void kernel_launch(void* const* d_in, const int* in_sizes, int n_in,
                              void* d_out, int out_size)
{
    const float* saE   = (const float*)d_in[0];
    const float* saD   = (const float*)d_in[1];
    const float* Wq    = (const float*)d_in[2];
    const float* bq    = (const float*)d_in[3];
    const float* Wk    = (const float*)d_in[4];
    const float* bk    = (const float*)d_in[5];
    const float* Wv    = (const float*)d_in[6];
    const float* bv    = (const float*)d_in[7];
    const float* gamma = (const float*)d_in[8];

    float* out = (float*)d_out;
    float* att = out + (size_t)BQ * CB * NPIX;   // attention after 'out' in tuple order

    size_t smA = (size_t)(64 * 258 + 64 * 64 + 64) * sizeof(float);
    size_t smB = (size_t)(64 * 33 + 32 * SKS + 4 * 16 * SPS) * sizeof(float);
    cudaFuncSetAttribute(qk_kernel,  cudaFuncAttributeMaxDynamicSharedMemorySize, (int)smA);
    cudaFuncSetAttribute(attn_kernel, cudaFuncAttributeMaxDynamicSharedMemorySize, (int)smB);

    qk_kernel<<<dim3(64, 4), 256, smA>>>(saD, Wq, bq, Wk, bk);
    attn_kernel<<<dim3(64, 4), 128, smB>>>(att);
    v_kernel<<<1024, 256>>>(saE, Wv, bv, gamma);
    out_kernel<<<2048, 256>>>(saE, gamma, out, att);
}

// round 2
// speedup vs baseline: 2.3676x; 2.3676x over previous
#include <cuda_runtime.h>
#include <cstdint>

#define NPIX 4096
#define CB   256
#define BQ   4
#define TM   128
#define SKS  136

// Scratch (device globals — no runtime allocation allowed)
__device__ float g_qk[BQ][64][NPIX];   // rows 0..31 = q, 32..63 = k   (4 MB)
__device__ float g_v[BQ][CB][NPIX];    // only used when gamma != 0    (16 MB)

__device__ __forceinline__ float tf32r(float v) {
    uint32_t u;
    asm("cvt.rna.tf32.f32 %0, %1;" : "=r"(u) : "f"(v));
    return __uint_as_float(u);
}

__device__ __forceinline__ void cpasync16(void* smem_dst, const void* gsrc) {
    uint32_t s = (uint32_t)__cvta_generic_to_shared(smem_dst);
    asm volatile("cp.async.cg.shared.global [%0], [%1], 16;" :: "r"(s), "l"(gsrc));
}
#define CP_COMMIT() asm volatile("cp.async.commit_group;" ::: "memory")
#define CP_WAIT0()  asm volatile("cp.async.wait_group 0;" ::: "memory")

// ---------------------------------------------------------------------------
// Kernel A: q = Wq·sa_D + bq, k = Wk·sa_D + bk  -> g_qk[b][d][n] (tf32-rounded)
// ---------------------------------------------------------------------------
__global__ void qk_kernel(const float* __restrict__ saD,
                          const float* __restrict__ Wq, const float* __restrict__ bq,
                          const float* __restrict__ Wk, const float* __restrict__ bk)
{
    extern __shared__ float sm[];
    float* sW = sm;                 // 64*258
    float* sX = sm + 64 * 258;      // 64*64
    float* sB = sX + 64 * 64;       // 64

    int b  = blockIdx.y;
    int n0 = blockIdx.x * 64;
    int t  = threadIdx.x;

    for (int i = t; i < 64 * 256; i += 256) {
        int d = i >> 8, c = i & 255;
        sW[d * 258 + c] = (d < 32) ? Wq[d * 256 + c] : Wk[(d - 32) * 256 + c];
    }
    if (t < 64) sB[t] = (t < 32) ? bq[t] : bk[t - 32];
    __syncthreads();

    int ty = t >> 4, tx = t & 15;
    float acc[4][4];
#pragma unroll
    for (int i = 0; i < 4; i++) {
        float bias = sB[ty + 16 * i];
#pragma unroll
        for (int j = 0; j < 4; j++) acc[i][j] = bias;
    }

    for (int c0 = 0; c0 < 256; c0 += 64) {
        __syncthreads();
#pragma unroll
        for (int r = 0; r < 4; r++) {
            int f  = t + 256 * r;
            int cc = f >> 4, nn = (f & 15) << 2;
            *(float4*)&sX[cc * 64 + nn] =
                *(const float4*)&saD[(size_t)(b * 256 + c0 + cc) * NPIX + n0 + nn];
        }
        __syncthreads();
#pragma unroll 4
        for (int cc = 0; cc < 64; cc++) {
            float w0 = sW[(ty     ) * 258 + c0 + cc];
            float w1 = sW[(ty + 16) * 258 + c0 + cc];
            float w2 = sW[(ty + 32) * 258 + c0 + cc];
            float w3 = sW[(ty + 48) * 258 + c0 + cc];
#pragma unroll
            for (int j = 0; j < 4; j++) {
                float x = sX[cc * 64 + tx + 16 * j];
                acc[0][j] += w0 * x; acc[1][j] += w1 * x;
                acc[2][j] += w2 * x; acc[3][j] += w3 * x;
            }
        }
    }
#pragma unroll
    for (int i = 0; i < 4; i++)
#pragma unroll
        for (int j = 0; j < 4; j++) {
            int d = ty + 16 * i;
            int n = n0 + tx + 16 * j;
            g_qk[b][d][n] = tf32r(acc[i][j]);
        }
}

// ---------------------------------------------------------------------------
// Kernel B: fused energy + softmax + attention (two-pass, tf32 mma)
// 256 threads (8 warps). Warp w owns ALL 64 rows (4 row-groups) and j in
// {2w, 2w+1} of 16 j-slots per 128-col K tile. B fragments loaded once per
// (j,kk) and reused across 4 row-group MMAs. cp.async double-buffered K.
// Pass-2 writes attention directly from registers as float2 (full sectors).
// ---------------------------------------------------------------------------
__device__ __forceinline__ void mma_tf32(float& c0, float& c1, float& c2, float& c3,
                                         const float a[4], float b0, float b1)
{
    asm volatile(
        "mma.sync.aligned.m16n8k8.row.col.f32.tf32.tf32.f32 "
        "{%0,%1,%2,%3}, {%4,%5,%6,%7}, {%8,%9}, {%0,%1,%2,%3};"
        : "+f"(c0), "+f"(c1), "+f"(c2), "+f"(c3)
        : "r"(__float_as_uint(a[0])), "r"(__float_as_uint(a[1])),
          "r"(__float_as_uint(a[2])), "r"(__float_as_uint(a[3])),
          "r"(__float_as_uint(b0)), "r"(__float_as_uint(b1)));
}

__global__ __launch_bounds__(256, 2) void attn_kernel(float* __restrict__ att)
{
    extern __shared__ float sm[];
    float* sQ   = sm;                    // 64*33
    float* sK0  = sQ + 64 * 33;          // 32*SKS
    float* sK1  = sK0 + 32 * SKS;        // 32*SKS
    float* sSum = sK1 + 32 * SKS;        // 8*64
    float* sInv = sSum + 8 * 64;         // 64

    int b  = blockIdx.y;
    int n0 = blockIdx.x * 64;
    int t  = threadIdx.x, w = t >> 5, l = t & 31;
    int lq = l >> 2, lr = l & 3;

    const float* qg = &g_qk[b][0][0];
    const float* kg = &g_qk[b][32][0];

    // Q tile [64 n][32 d], transposed from [d][n]
    for (int i = t; i < 64 * 32; i += 256) {
        int n = i & 63, d = i >> 6;
        sQ[n * 33 + d] = qg[(size_t)d * NPIX + n0 + n];
    }
    __syncthreads();

    // A fragments: 4 row-groups x 4 k-steps
    float aF[4][4][4];
#pragma unroll
    for (int rg = 0; rg < 4; rg++) {
        int r = rg * 16 + lq;
#pragma unroll
        for (int kk = 0; kk < 4; kk++) {
            int c = kk * 8 + lr;
            aF[rg][kk][0] = sQ[r * 33 + c];
            aF[rg][kk][1] = sQ[(r + 8) * 33 + c];
            aF[rg][kk][2] = sQ[r * 33 + c + 4];
            aF[rg][kk][3] = sQ[(r + 8) * 33 + c + 4];
        }
    }

    // per-tile K copy via cp.async (4 x 16B per thread)
    auto cp_tile = [&](int m0, float* dst) {
#pragma unroll
        for (int r = 0; r < 4; r++) {
            int f = t + 256 * r;                 // 0..1023 float4 slots
            int d = f >> 5, mm = (f & 31) << 2;
            cpasync16(&dst[d * SKS + mm], &kg[(size_t)d * NPIX + m0 + mm]);
        }
        CP_COMMIT();
    };

    int j0 = 2 * w;

    // ---- pass 1: row sums of exp(energy) ----
    float s[4][2];
#pragma unroll
    for (int rg = 0; rg < 4; rg++) s[rg][0] = s[rg][1] = 0.f;

    cp_tile(0, sK0);
    for (int tile = 0; tile < 32; tile++) {
        float* cur = (tile & 1) ? sK1 : sK0;
        float* nxt = (tile & 1) ? sK0 : sK1;
        CP_WAIT0();
        __syncthreads();
        if (tile < 31) cp_tile((tile + 1) * TM, nxt);
#pragma unroll
        for (int jj = 0; jj < 2; jj++) {
            int j = j0 + jj;
            float b0[4], b1[4];
#pragma unroll
            for (int kk = 0; kk < 4; kk++) {
                b0[kk] = cur[(kk * 8 + lr) * SKS + j * 8 + lq];
                b1[kk] = cur[(kk * 8 + lr + 4) * SKS + j * 8 + lq];
            }
#pragma unroll
            for (int rg = 0; rg < 4; rg++) {
                float c0 = 0.f, c1 = 0.f, c2 = 0.f, c3 = 0.f;
#pragma unroll
                for (int kk = 0; kk < 4; kk++)
                    mma_tf32(c0, c1, c2, c3, aF[rg][kk], b0[kk], b1[kk]);
                s[rg][0] += __expf(c0) + __expf(c1);
                s[rg][1] += __expf(c2) + __expf(c3);
            }
        }
    }
    // reduce over lanes sharing a row (l&3), then across warps via smem
#pragma unroll
    for (int rg = 0; rg < 4; rg++) {
#pragma unroll
        for (int h = 0; h < 2; h++) {
            s[rg][h] += __shfl_xor_sync(0xffffffffu, s[rg][h], 1);
            s[rg][h] += __shfl_xor_sync(0xffffffffu, s[rg][h], 2);
        }
    }
    if (lr == 0) {
#pragma unroll
        for (int rg = 0; rg < 4; rg++) {
            sSum[w * 64 + rg * 16 + lq]     = s[rg][0];
            sSum[w * 64 + rg * 16 + 8 + lq] = s[rg][1];
        }
    }
    __syncthreads();
    if (t < 64) {
        float tot = 0.f;
#pragma unroll
        for (int ww = 0; ww < 8; ww++) tot += sSum[ww * 64 + t];
        sInv[t] = 1.f / tot;
    }
    __syncthreads();

    float inv[4][2];
#pragma unroll
    for (int rg = 0; rg < 4; rg++) {
        inv[rg][0] = sInv[rg * 16 + lq];
        inv[rg][1] = sInv[rg * 16 + 8 + lq];
    }

    // ---- pass 2: recompute, normalize, store directly ----
    cp_tile(0, sK0);
    for (int tile = 0; tile < 32; tile++) {
        int m0 = tile * TM;
        float* cur = (tile & 1) ? sK1 : sK0;
        float* nxt = (tile & 1) ? sK0 : sK1;
        CP_WAIT0();
        __syncthreads();
        if (tile < 31) cp_tile((tile + 1) * TM, nxt);
#pragma unroll
        for (int jj = 0; jj < 2; jj++) {
            int j = j0 + jj;
            float b0[4], b1[4];
#pragma unroll
            for (int kk = 0; kk < 4; kk++) {
                b0[kk] = cur[(kk * 8 + lr) * SKS + j * 8 + lq];
                b1[kk] = cur[(kk * 8 + lr + 4) * SKS + j * 8 + lq];
            }
#pragma unroll
            for (int rg = 0; rg < 4; rg++) {
                float c0 = 0.f, c1 = 0.f, c2 = 0.f, c3 = 0.f;
#pragma unroll
                for (int kk = 0; kk < 4; kk++)
                    mma_tf32(c0, c1, c2, c3, aF[rg][kk], b0[kk], b1[kk]);
                float p0 = __expf(c0) * inv[rg][0];
                float p1 = __expf(c1) * inv[rg][0];
                float p2 = __expf(c2) * inv[rg][1];
                float p3 = __expf(c3) * inv[rg][1];
                size_t base = ((size_t)(b * NPIX + n0 + rg * 16 + lq)) * NPIX
                              + m0 + j * 8 + lr * 2;
                *(float2*)&att[base]            = make_float2(p0, p1);
                *(float2*)&att[base + 8 * NPIX] = make_float2(p2, p3);
            }
        }
    }
}

// ---------------------------------------------------------------------------
// Kernel C: v = Wv·sa_E + bv  (only when gamma != 0 — exact skip otherwise)
// ---------------------------------------------------------------------------
__global__ void v_kernel(const float* __restrict__ saE,
                         const float* __restrict__ Wv,
                         const float* __restrict__ bv,
                         const float* __restrict__ gamma)
{
    if (gamma[0] == 0.f) return;
    int total = BQ * CB * NPIX;
    for (int idx = blockIdx.x * blockDim.x + threadIdx.x; idx < total;
         idx += gridDim.x * blockDim.x) {
        int m  = idx & (NPIX - 1);
        int c  = (idx >> 12) & 255;
        int bb = idx >> 20;
        float s = bv[c];
        for (int cc = 0; cc < 256; cc++)
            s += Wv[c * 256 + cc] * saE[(size_t)(bb * 256 + cc) * NPIX + m];
        g_v[bb][c][m] = s;
    }
}

// ---------------------------------------------------------------------------
// Kernel D: out = gamma*(V·A^T) + sa_E.  gamma==0 -> exact copy (MLP=4 batched)
// ---------------------------------------------------------------------------
__global__ void out_kernel(const float* __restrict__ saE,
                           const float* __restrict__ gamma,
                           float* __restrict__ out,
                           const float* __restrict__ att)
{
    float g = gamma[0];
    const int nvec = (BQ * CB * NPIX) / 4;  // 1048576 float4s
    if (g == 0.f) {
        int i = blockIdx.x * blockDim.x + threadIdx.x;   // grid covers nvec/4
        const int stride = nvec / 4;                     // 262144
        float4 a = ((const float4*)saE)[i];
        float4 b2 = ((const float4*)saE)[i + stride];
        float4 c = ((const float4*)saE)[i + 2 * stride];
        float4 d = ((const float4*)saE)[i + 3 * stride];
        ((float4*)out)[i]              = a;
        ((float4*)out)[i + stride]     = b2;
        ((float4*)out)[i + 2 * stride] = c;
        ((float4*)out)[i + 3 * stride] = d;
    } else {
        for (int i = blockIdx.x * blockDim.x + threadIdx.x; i < nvec;
             i += gridDim.x * blockDim.x) {
            int base = i * 4;
            int n  = base & (NPIX - 1);
            int c  = (base >> 12) & 255;
            int bb = base >> 20;
            float4 e = ((const float4*)saE)[i];
            const float* vrow = &g_v[bb][c][0];
            float rr[4];
#pragma unroll
            for (int jj = 0; jj < 4; jj++) {
                const float* arow = att + (size_t)(bb * NPIX + n + jj) * NPIX;
                float s = 0.f;
                for (int m = 0; m < NPIX; m++) s += vrow[m] * arow[m];
                rr[jj] = g * s + (&e.x)[jj];
            }
            ((float4*)out)[i] = make_float4(rr[0], rr[1], rr[2], rr[3]);
        }
    }
}

// ---------------------------------------------------------------------------
extern "C" void kernel_launch(void* const* d_in, const int* in_sizes, int n_in,
                              void* d_out, int out_size)
{
    const float* saE   = (const float*)d_in[0];
    const float* saD   = (const float*)d_in[1];
    const float* Wq    = (const float*)d_in[2];
    const float* bq    = (const float*)d_in[3];
    const float* Wk    = (const float*)d_in[4];
    const float* bk    = (const float*)d_in[5];
    const float* Wv    = (const float*)d_in[6];
    const float* bv    = (const float*)d_in[7];
    const float* gamma = (const float*)d_in[8];

    float* out = (float*)d_out;
    float* att = out + (size_t)BQ * CB * NPIX;

    size_t smA = (size_t)(64 * 258 + 64 * 64 + 64) * sizeof(float);
    size_t smB = (size_t)(64 * 33 + 2 * 32 * SKS + 8 * 64 + 64) * sizeof(float);
    cudaFuncSetAttribute(qk_kernel,   cudaFuncAttributeMaxDynamicSharedMemorySize, (int)smA);
    cudaFuncSetAttribute(attn_kernel, cudaFuncAttributeMaxDynamicSharedMemorySize, (int)smB);

    qk_kernel<<<dim3(64, 4), 256, smA>>>(saD, Wq, bq, Wk, bk);
    attn_kernel<<<dim3(64, 4), 256, smB>>>(att);
    v_kernel<<<1024, 256>>>(saE, Wv, bv, gamma);
    out_kernel<<<1024, 256>>>(saE, gamma, out, att);
}

// round 4
// speedup vs baseline: 2.5028x; 1.0571x over previous
#include <cuda_runtime.h>
#include <cuda_bf16.h>
#include <cstdint>

#define NPIX 4096
#define CB   256
#define BQ   4
#define TM   128
#define SKS  136
#define SKH  40    // bf16 K-tile stride in halves (conflict-free)

// Scratch (device globals — no runtime allocation allowed)
__device__ float g_qk[BQ][64][NPIX];              // rows 0..31 = q, 32..63 = k (tf32)
__device__ __nv_bfloat16 g_kh[BQ][NPIX][32];      // k transposed [m][d], bf16 (1 MB)
__device__ float g_v[BQ][CB][NPIX];               // only when gamma != 0

__device__ __forceinline__ float tf32r(float v) {
    uint32_t u;
    asm("cvt.rna.tf32.f32 %0, %1;" : "=r"(u) : "f"(v));
    return __uint_as_float(u);
}

__device__ __forceinline__ void cpasync16(void* smem_dst, const void* gsrc) {
    uint32_t s = (uint32_t)__cvta_generic_to_shared(smem_dst);
    asm volatile("cp.async.cg.shared.global [%0], [%1], 16;" :: "r"(s), "l"(gsrc));
}
#define CP_COMMIT() asm volatile("cp.async.commit_group;" ::: "memory")
#define CP_WAIT0()  asm volatile("cp.async.wait_group 0;" ::: "memory")

// ---------------------------------------------------------------------------
// Kernel A: q = Wq·sa_D + bq, k = Wk·sa_D + bk
//   -> g_qk[b][d][n] tf32 (pass-2 source) and g_kh[b][m][d] bf16 (pass-1 source)
// ---------------------------------------------------------------------------
__global__ void qk_kernel(const float* __restrict__ saD,
                          const float* __restrict__ Wq, const float* __restrict__ bq,
                          const float* __restrict__ Wk, const float* __restrict__ bk)
{
    extern __shared__ float sm[];
    float* sW = sm;                 // 64*258
    float* sX = sm + 64 * 258;      // 64*64 (reused as bf16 transpose buf later)
    float* sB = sX + 64 * 64;       // 64

    int b  = blockIdx.y;
    int n0 = blockIdx.x * 64;
    int t  = threadIdx.x;

    for (int i = t; i < 64 * 256; i += 256) {
        int d = i >> 8, c = i & 255;
        sW[d * 258 + c] = (d < 32) ? Wq[d * 256 + c] : Wk[(d - 32) * 256 + c];
    }
    if (t < 64) sB[t] = (t < 32) ? bq[t] : bk[t - 32];
    __syncthreads();

    int ty = t >> 4, tx = t & 15;
    float acc[4][4];
#pragma unroll
    for (int i = 0; i < 4; i++) {
        float bias = sB[ty + 16 * i];
#pragma unroll
        for (int j = 0; j < 4; j++) acc[i][j] = bias;
    }

    for (int c0 = 0; c0 < 256; c0 += 64) {
        __syncthreads();
#pragma unroll
        for (int r = 0; r < 4; r++) {
            int f  = t + 256 * r;
            int cc = f >> 4, nn = (f & 15) << 2;
            *(float4*)&sX[cc * 64 + nn] =
                *(const float4*)&saD[(size_t)(b * 256 + c0 + cc) * NPIX + n0 + nn];
        }
        __syncthreads();
#pragma unroll 4
        for (int cc = 0; cc < 64; cc++) {
            float w0 = sW[(ty     ) * 258 + c0 + cc];
            float w1 = sW[(ty + 16) * 258 + c0 + cc];
            float w2 = sW[(ty + 32) * 258 + c0 + cc];
            float w3 = sW[(ty + 48) * 258 + c0 + cc];
#pragma unroll
            for (int j = 0; j < 4; j++) {
                float x = sX[cc * 64 + tx + 16 * j];
                acc[0][j] += w0 * x; acc[1][j] += w1 * x;
                acc[2][j] += w2 * x; acc[3][j] += w3 * x;
            }
        }
    }
    // tf32 store (q + k)
#pragma unroll
    for (int i = 0; i < 4; i++)
#pragma unroll
        for (int j = 0; j < 4; j++)
            g_qk[b][ty + 16 * i][n0 + tx + 16 * j] = tf32r(acc[i][j]);

    // bf16 transposed k store: stage [n][d] in smem (reuse sX), then coalesced out
    __syncthreads();
    __nv_bfloat16* sT = (__nv_bfloat16*)sX;   // 64 x SKH halves
#pragma unroll
    for (int i = 2; i < 4; i++)
#pragma unroll
        for (int j = 0; j < 4; j++)
            sT[(tx + 16 * j) * SKH + ty + 16 * (i - 2)] = __float2bfloat16(acc[i][j]);
    __syncthreads();
    {
        int r = t >> 2, p = t & 3;
        uint4 v = *(uint4*)&sT[r * SKH + p * 8];
        *(uint4*)&g_kh[b][n0 + r][p * 8] = v;
    }
}

// ---------------------------------------------------------------------------
// Kernel B: fused energy + softmax + attention.
// Pass 1 (denominators): bf16 m16n8k16 mma on pre-transposed bf16 K tiles.
// Pass 2 (values): tf32 m16n8k8 mma, direct float2 stores.
// 8 warps; warp w owns j in {2w,2w+1}, all 64 rows. cp.async double buffer.
// ---------------------------------------------------------------------------
__device__ __forceinline__ void mma_tf32(float& c0, float& c1, float& c2, float& c3,
                                         const float a[4], float b0, float b1)
{
    asm volatile(
        "mma.sync.aligned.m16n8k8.row.col.f32.tf32.tf32.f32 "
        "{%0,%1,%2,%3}, {%4,%5,%6,%7}, {%8,%9}, {%0,%1,%2,%3};"
        : "+f"(c0), "+f"(c1), "+f"(c2), "+f"(c3)
        : "r"(__float_as_uint(a[0])), "r"(__float_as_uint(a[1])),
          "r"(__float_as_uint(a[2])), "r"(__float_as_uint(a[3])),
          "r"(__float_as_uint(b0)), "r"(__float_as_uint(b1)));
}

__device__ __forceinline__ void mma_bf16(float& c0, float& c1, float& c2, float& c3,
                                         const uint32_t a[4], uint32_t b0, uint32_t b1)
{
    asm volatile(
        "mma.sync.aligned.m16n8k16.row.col.f32.bf16.bf16.f32 "
        "{%0,%1,%2,%3}, {%4,%5,%6,%7}, {%8,%9}, {%0,%1,%2,%3};"
        : "+f"(c0), "+f"(c1), "+f"(c2), "+f"(c3)
        : "r"(a[0]), "r"(a[1]), "r"(a[2]), "r"(a[3]), "r"(b0), "r"(b1));
}

__device__ __forceinline__ uint32_t packbf(float lo, float hi) {
    __nv_bfloat162 h = __floats2bfloat162_rn(lo, hi);
    return *(uint32_t*)&h;
}

__global__ __launch_bounds__(256, 2) void attn_kernel(float* __restrict__ att)
{
    extern __shared__ float sm[];
    float* sQ  = sm;                             // 64*33
    float* sK0 = sm + 64 * 33;                   // union zone: tf32 K (pass 2)
    float* sK1 = sK0 + 32 * SKS;
    __nv_bfloat16* sKh0 = (__nv_bfloat16*)sK0;   // union zone: bf16 K (pass 1)
    __nv_bfloat16* sKh1 = sKh0 + 128 * SKH;
    float* sSum = sK1 + 32 * SKS;                // 8*64
    float* sInv = sSum + 8 * 64;                 // 64

    int b  = blockIdx.y;
    int n0 = blockIdx.x * 64;
    int t  = threadIdx.x, w = t >> 5, l = t & 31;
    int lq = l >> 2, lr = l & 3;
    int j0 = 2 * w;

    const float* qg = &g_qk[b][0][0];
    const float* kg = &g_qk[b][32][0];
    const __nv_bfloat16* khg = &g_kh[b][0][0];

    // Q tile [64 n][32 d] (tf32 floats), transposed from [d][n]
    for (int i = t; i < 64 * 32; i += 256) {
        int n = i & 63, d = i >> 6;
        sQ[n * 33 + d] = qg[(size_t)d * NPIX + n0 + n];
    }
    __syncthreads();

    // ---- pass 1: bf16 denominators ----
    // A fragments bf16: 4 row-groups x 2 k16-chunks x 4 regs
    uint32_t aH[4][2][4];
#pragma unroll
    for (int rg = 0; rg < 4; rg++) {
        int r = rg * 16 + lq;
#pragma unroll
        for (int kk = 0; kk < 2; kk++) {
            int c = kk * 16 + lr * 2;
            aH[rg][kk][0] = packbf(sQ[r * 33 + c],           sQ[r * 33 + c + 1]);
            aH[rg][kk][1] = packbf(sQ[(r + 8) * 33 + c],     sQ[(r + 8) * 33 + c + 1]);
            aH[rg][kk][2] = packbf(sQ[r * 33 + c + 8],       sQ[r * 33 + c + 9]);
            aH[rg][kk][3] = packbf(sQ[(r + 8) * 33 + c + 8], sQ[(r + 8) * 33 + c + 9]);
        }
    }

    auto cp_tile_h = [&](int m0, __nv_bfloat16* dst) {
#pragma unroll
        for (int r = 0; r < 2; r++) {
            int f = t + 256 * r;                 // 0..511 16B chunks
            int m = f >> 2, p = f & 3;
            cpasync16(&dst[m * SKH + p * 8], &khg[(size_t)(m0 + m) * 32 + p * 8]);
        }
        CP_COMMIT();
    };

    float s[4][2];
#pragma unroll
    for (int rg = 0; rg < 4; rg++) s[rg][0] = s[rg][1] = 0.f;

    cp_tile_h(0, sKh0);
    for (int tile = 0; tile < 32; tile++) {
        __nv_bfloat16* cur = (tile & 1) ? sKh1 : sKh0;
        __nv_bfloat16* nxt = (tile & 1) ? sKh0 : sKh1;
        CP_WAIT0();
        __syncthreads();
        if (tile < 31) cp_tile_h((tile + 1) * TM, nxt);
#pragma unroll
        for (int jj = 0; jj < 2; jj++) {
            int j = j0 + jj;
            uint32_t b0[2], b1[2];
#pragma unroll
            for (int kk = 0; kk < 2; kk++) {
                b0[kk] = *(uint32_t*)&cur[(j * 8 + lq) * SKH + kk * 16 + lr * 2];
                b1[kk] = *(uint32_t*)&cur[(j * 8 + lq) * SKH + kk * 16 + lr * 2 + 8];
            }
#pragma unroll
            for (int rg = 0; rg < 4; rg++) {
                float c0 = 0.f, c1 = 0.f, c2 = 0.f, c3 = 0.f;
                mma_bf16(c0, c1, c2, c3, aH[rg][0], b0[0], b1[0]);
                mma_bf16(c0, c1, c2, c3, aH[rg][1], b0[1], b1[1]);
                s[rg][0] += __expf(c0) + __expf(c1);
                s[rg][1] += __expf(c2) + __expf(c3);
            }
        }
        __syncthreads();
    }
#pragma unroll
    for (int rg = 0; rg < 4; rg++)
#pragma unroll
        for (int h = 0; h < 2; h++) {
            s[rg][h] += __shfl_xor_sync(0xffffffffu, s[rg][h], 1);
            s[rg][h] += __shfl_xor_sync(0xffffffffu, s[rg][h], 2);
        }
    if (lr == 0)
#pragma unroll
        for (int rg = 0; rg < 4; rg++) {
            sSum[w * 64 + rg * 16 + lq]     = s[rg][0];
            sSum[w * 64 + rg * 16 + 8 + lq] = s[rg][1];
        }
    __syncthreads();
    if (t < 64) {
        float tot = 0.f;
#pragma unroll
        for (int ww = 0; ww < 8; ww++) tot += sSum[ww * 64 + t];
        sInv[t] = 1.f / tot;
    }
    __syncthreads();

    float inv[4][2];
#pragma unroll
    for (int rg = 0; rg < 4; rg++) {
        inv[rg][0] = sInv[rg * 16 + lq];
        inv[rg][1] = sInv[rg * 16 + 8 + lq];
    }

    // ---- pass 2: tf32 values ----
    float aF[4][4][4];
#pragma unroll
    for (int rg = 0; rg < 4; rg++) {
        int r = rg * 16 + lq;
#pragma unroll
        for (int kk = 0; kk < 4; kk++) {
            int c = kk * 8 + lr;
            aF[rg][kk][0] = sQ[r * 33 + c];
            aF[rg][kk][1] = sQ[(r + 8) * 33 + c];
            aF[rg][kk][2] = sQ[r * 33 + c + 4];
            aF[rg][kk][3] = sQ[(r + 8) * 33 + c + 4];
        }
    }

    auto cp_tile = [&](int m0, float* dst) {
#pragma unroll
        for (int r = 0; r < 4; r++) {
            int f = t + 256 * r;
            int d = f >> 5, mm = (f & 31) << 2;
            cpasync16(&dst[d * SKS + mm], &kg[(size_t)d * NPIX + m0 + mm]);
        }
        CP_COMMIT();
    };

    __syncthreads();   // pass-1 buffers dead before union reuse
    cp_tile(0, sK0);
    for (int tile = 0; tile < 32; tile++) {
        int m0 = tile * TM;
        float* cur = (tile & 1) ? sK1 : sK0;
        float* nxt = (tile & 1) ? sK0 : sK1;
        CP_WAIT0();
        __syncthreads();
        if (tile < 31) cp_tile((tile + 1) * TM, nxt);
#pragma unroll
        for (int jj = 0; jj < 2; jj++) {
            int j = j0 + jj;
            float b0[4], b1[4];
#pragma unroll
            for (int kk = 0; kk < 4; kk++) {
                b0[kk] = cur[(kk * 8 + lr) * SKS + j * 8 + lq];
                b1[kk] = cur[(kk * 8 + lr + 4) * SKS + j * 8 + lq];
            }
#pragma unroll
            for (int rg = 0; rg < 4; rg++) {
                float c0 = 0.f, c1 = 0.f, c2 = 0.f, c3 = 0.f;
#pragma unroll
                for (int kk = 0; kk < 4; kk++)
                    mma_tf32(c0, c1, c2, c3, aF[rg][kk], b0[kk], b1[kk]);
                float p0 = __expf(c0) * inv[rg][0];
                float p1 = __expf(c1) * inv[rg][0];
                float p2 = __expf(c2) * inv[rg][1];
                float p3 = __expf(c3) * inv[rg][1];
                size_t base = ((size_t)(b * NPIX + n0 + rg * 16 + lq)) * NPIX
                              + m0 + j * 8 + lr * 2;
                *(float2*)&att[base]            = make_float2(p0, p1);
                *(float2*)&att[base + 8 * NPIX] = make_float2(p2, p3);
            }
        }
    }
}

// ---------------------------------------------------------------------------
// Kernel C: v = Wv·sa_E + bv  (only when gamma != 0 — exact skip otherwise)
// ---------------------------------------------------------------------------
__global__ void v_kernel(const float* __restrict__ saE,
                         const float* __restrict__ Wv,
                         const float* __restrict__ bv,
                         const float* __restrict__ gamma)
{
    if (gamma[0] == 0.f) return;
    int total = BQ * CB * NPIX;
    for (int idx = blockIdx.x * blockDim.x + threadIdx.x; idx < total;
         idx += gridDim.x * blockDim.x) {
        int m  = idx & (NPIX - 1);
        int c  = (idx >> 12) & 255;
        int bb = idx >> 20;
        float s = bv[c];
        for (int cc = 0; cc < 256; cc++)
            s += Wv[c * 256 + cc] * saE[(size_t)(bb * 256 + cc) * NPIX + m];
        g_v[bb][c][m] = s;
    }
}

// ---------------------------------------------------------------------------
// Kernel D: out = gamma*(V·A^T) + sa_E.  gamma==0 -> exact copy
// ---------------------------------------------------------------------------
__global__ void out_kernel(const float* __restrict__ saE,
                           const float* __restrict__ gamma,
                           float* __restrict__ out,
                           const float* __restrict__ att)
{
    float g = gamma[0];
    const int nvec = (BQ * CB * NPIX) / 4;  // 1048576 float4s
    if (g == 0.f) {
        int i = blockIdx.x * blockDim.x + threadIdx.x;   // 524288 threads
        const int stride = nvec / 2;
        float4 a = ((const float4*)saE)[i];
        float4 b2 = ((const float4*)saE)[i + stride];
        ((float4*)out)[i]          = a;
        ((float4*)out)[i + stride] = b2;
    } else {
        for (int i = blockIdx.x * blockDim.x + threadIdx.x; i < nvec;
             i += gridDim.x * blockDim.x) {
            int base = i * 4;
            int n  = base & (NPIX - 1);
            int c  = (base >> 12) & 255;
            int bb = base >> 20;
            float4 e = ((const float4*)saE)[i];
            const float* vrow = &g_v[bb][c][0];
            float rr[4];
#pragma unroll
            for (int jj = 0; jj < 4; jj++) {
                const float* arow = att + (size_t)(bb * NPIX + n + jj) * NPIX;
                float s = 0.f;
                for (int m = 0; m < NPIX; m++) s += vrow[m] * arow[m];
                rr[jj] = g * s + (&e.x)[jj];
            }
            ((float4*)out)[i] = make_float4(rr[0], rr[1], rr[2], rr[3]);
        }
    }
}

// ---------------------------------------------------------------------------
extern "C" void kernel_launch(void* const* d_in, const int* in_sizes, int n_in,
                              void* d_out, int out_size)
{
    const float* saE   = (const float*)d_in[0];
    const float* saD   = (const float*)d_in[1];
    const float* Wq    = (const float*)d_in[2];
    const float* bq    = (const float*)d_in[3];
    const float* Wk    = (const float*)d_in[4];
    const float* bk    = (const float*)d_in[5];
    const float* Wv    = (const float*)d_in[6];
    const float* bv    = (const float*)d_in[7];
    const float* gamma = (const float*)d_in[8];

    float* out = (float*)d_out;
    float* att = out + (size_t)BQ * CB * NPIX;

    size_t smA = (size_t)(64 * 258 + 64 * 64 + 64) * sizeof(float);
    size_t smB = (size_t)(64 * 33 + 2 * 32 * SKS + 8 * 64 + 64) * sizeof(float);
    cudaFuncSetAttribute(qk_kernel,   cudaFuncAttributeMaxDynamicSharedMemorySize, (int)smA);
    cudaFuncSetAttribute(attn_kernel, cudaFuncAttributeMaxDynamicSharedMemorySize, (int)smB);

    qk_kernel<<<dim3(64, 4), 256, smA>>>(saD, Wq, bq, Wk, bk);
    attn_kernel<<<dim3(64, 4), 256, smB>>>(att);
    v_kernel<<<1024, 256>>>(saE, Wv, bv, gamma);
    out_kernel<<<2048, 256>>>(saE, gamma, out, att);
}